// round 15
// baseline (speedup 1.0000x reference)
#include <cuda_runtime.h>

constexpr int C = 32, D = 64, H = 192, W = 160;
constexpr int DHW = D * H * W;     // 1,966,080

constexpr int W_T = 32;            // tile width (w)
constexpr int D_T = 16;            // tile depth (d)
constexpr int SP  = D_T + 1;       // padded smem row (17)

// Block: 512 threads = 32 (w lanes) x 16 (d rows). One point per thread.
// Compute: lanes along w -> coalesced gathers. Write: smem transpose ->
// stores contiguous in d. 2 channels per barrier, 4-buffer smem ring.
// launch_bounds(512,3): caps regs ~42 -> 48 warps/SM.
__global__ __launch_bounds__(512, 3)
void affine_grid_sample_kernel(const float* __restrict__ in,
                               const float* __restrict__ theta,
                               float* __restrict__ out)
{
    __shared__ float s[4][W_T][SP];

    const int tid = threadIdx.x;
    const int wl  = tid & 31;                   // 0..31 (w lane)
    const int ty  = tid >> 5;                   // 0..15 (d row)
    const int w   = blockIdx.x * W_T + wl;      // 0..159
    const int d0  = blockIdx.y * D_T;           // 0,16,32,48
    const int h   = blockIdx.z;                 // 0..191
    const int d   = d0 + ty;

    float t[12];
#pragma unroll
    for (int i = 0; i < 12; i++) t[i] = __ldg(theta + i);

    const float xn = -1.0f + 2.0f * (float)w / (float)(W - 1);
    const float yn = -1.0f + 2.0f * (float)h / (float)(H - 1);
    const float zn = -1.0f + 2.0f * (float)d / (float)(D - 1);

    const float gx = t[0] * xn + t[1] * yn + t[2]  * zn + t[3];
    const float gy = t[4] * xn + t[5] * yn + t[6]  * zn + t[7];
    const float gz = t[8] * xn + t[9] * yn + t[10] * zn + t[11];

    const float px = (gx + 1.0f) * 0.5f * (float)(W - 1);
    const float py = (gy + 1.0f) * 0.5f * (float)(H - 1);
    const float pz = (gz + 1.0f) * 0.5f * (float)(D - 1);

    const float fx = floorf(px), fy = floorf(py), fz = floorf(pz);
    const int x0 = (int)fx, y0 = (int)fy, z0 = (int)fz;
    const int x1 = x0 + 1,  y1 = y0 + 1,  z1 = z0 + 1;
    const float wx = px - fx, wy = py - fy, wz = pz - fz;

    // Zeros padding is separable: fold validity into per-axis weights.
    const float vx0 = (x0 >= 0 && x0 < W) ? (1.0f - wx) : 0.0f;
    const float vx1 = (x1 >= 0 && x1 < W) ? wx          : 0.0f;
    const float vy0 = (y0 >= 0 && y0 < H) ? (1.0f - wy) : 0.0f;
    const float vy1 = (y1 >= 0 && y1 < H) ? wy          : 0.0f;
    const float vz0 = (z0 >= 0 && z0 < D) ? (1.0f - wz) : 0.0f;
    const float vz1 = (z1 >= 0 && z1 < D) ? wz          : 0.0f;

    const int xc0 = min(max(x0, 0), W - 1);
    const int xc1 = min(max(x1, 0), W - 1);
    const int yc0 = min(max(y0, 0), H - 1);
    const int yc1 = min(max(y1, 0), H - 1);
    const int zc0 = min(max(z0, 0), D - 1);
    const int zc1 = min(max(z1, 0), D - 1);

    // 4 row bases with xc0 folded in; dx = xc1-xc0 (0 at clamped edge).
    const int a0 = (zc0 * H + yc0) * W + xc0;
    const int a1 = (zc0 * H + yc1) * W + xc0;
    const int a2 = (zc1 * H + yc0) * W + xc0;
    const int a3 = (zc1 * H + yc1) * W + xc0;
    const int dd = xc1 - xc0;

    const float zy0 = vz0 * vy0;
    const float zy1 = vz0 * vy1;
    const float zy2 = vz1 * vy0;
    const float zy3 = vz1 * vy1;

    // Write-phase role: dl = tid%16 (d within tile), w_r = tid/16 (0..31).
    const int dl  = tid & 15;
    const int w_r = tid >> 4;
    const int w_out = blockIdx.x * W_T + w_r;
    float* op = out + ((size_t)(w_out * H + h) * C) * (size_t)D + d0 + dl;

    const float* ip = in;
    for (int c = 0; c < C; c += 2) {
        const int b0 = c & 3;   // ring buffers b0, b0+1

        // ---- compute phase: 2 channels, 16 independent gathers ----
#pragma unroll
        for (int ch = 0; ch < 2; ch++) {
            const float* ipc = ip + ch * DHW;

            const float v00 = __ldg(ipc + a0);
            const float v01 = __ldg(ipc + a0 + dd);
            const float v10 = __ldg(ipc + a1);
            const float v11 = __ldg(ipc + a1 + dd);
            const float v20 = __ldg(ipc + a2);
            const float v21 = __ldg(ipc + a2 + dd);
            const float v30 = __ldg(ipc + a3);
            const float v31 = __ldg(ipc + a3 + dd);

            float r;
            r =          zy0 * fmaf(vx1, v01, vx0 * v00);
            r = fmaf(zy1, fmaf(vx1, v11, vx0 * v10), r);
            r = fmaf(zy2, fmaf(vx1, v21, vx0 * v20), r);
            r = fmaf(zy3, fmaf(vx1, v31, vx0 * v30), r);

            s[b0 + ch][wl][ty] = r;
        }

        __syncthreads();   // bufs filled; also fences their reuse next pass

        // ---- write phase: 1 store/thread/channel, contiguous in d ----
#pragma unroll
        for (int ch = 0; ch < 2; ch++) {
            op[(size_t)(c + ch) * D] = s[b0 + ch][w_r][dl];
        }

        ip += 2 * DHW;
    }
}

extern "C" void kernel_launch(void* const* d_in, const int* in_sizes, int n_in,
                              void* d_out, int out_size)
{
    const float* in    = (const float*)d_in[0];   // [1,32,64,192,160]
    const float* theta = (const float*)d_in[1];   // [12]
    float* out = (float*)d_out;                   // [1,160,192,32,64]

    dim3 block(512);
    dim3 grid(W / W_T, D / D_T, H);   // 5 x 4 x 192 = 3840
    affine_grid_sample_kernel<<<grid, block>>>(in, theta, out);
}

// round 16
// speedup vs baseline: 1.3486x; 1.3486x over previous
#include <cuda_runtime.h>

constexpr int C = 32, D = 64, H = 192, W = 160;
constexpr int DHW = D * H * W;     // 1,966,080

constexpr int W_T = 32;            // tile width (w)
constexpr int D_T = 16;            // tile depth (d)
constexpr int PTS = 2;             // d-points per thread
constexpr int SP  = D_T + 1;       // padded smem row (17)
constexpr int CH  = 4;             // channels per barrier

// Block: 32 (w) x 8 (d-rows) = 256 threads, 2 points each -> 32x16 tile.
// Compute: lanes along w (coalesced gathers). Write: smem transpose ->
// stores contiguous in d. 4 channels per barrier, 8-buffer smem ring.
__global__ __launch_bounds__(256, 4)
void affine_grid_sample_kernel(const float* __restrict__ in,
                               const float* __restrict__ theta,
                               float* __restrict__ out)
{
    __shared__ float s[2 * CH][W_T][SP];

    const int wl = threadIdx.x;                 // 0..31
    const int ty = threadIdx.y;                 // 0..7
    const int w  = blockIdx.x * W_T + wl;       // 0..159
    const int d0 = blockIdx.y * D_T;            // 0,16,32,48
    const int h  = blockIdx.z;                  // 0..191

    float t[12];
#pragma unroll
    for (int i = 0; i < 12; i++) t[i] = __ldg(theta + i);

    const float xn = -1.0f + 2.0f * (float)w / (float)(W - 1);
    const float yn = -1.0f + 2.0f * (float)h / (float)(H - 1);

    // Per-point geometry held in registers across the channel loop.
    int   adr[PTS][4];       // 4 (z,y)-row bases with xc0 folded in
    int   dx[PTS];           // xc1-xc0 (0 at clamped edge, else 1)
    float zy[PTS][4];        // masked az*ay products
    float ax0[PTS], ax1[PTS];

#pragma unroll
    for (int p = 0; p < PTS; p++) {
        const int d = d0 + ty + 8 * p;
        const float zn = -1.0f + 2.0f * (float)d / (float)(D - 1);

        const float gx = t[0] * xn + t[1] * yn + t[2]  * zn + t[3];
        const float gy = t[4] * xn + t[5] * yn + t[6]  * zn + t[7];
        const float gz = t[8] * xn + t[9] * yn + t[10] * zn + t[11];

        const float px = (gx + 1.0f) * 0.5f * (float)(W - 1);
        const float py = (gy + 1.0f) * 0.5f * (float)(H - 1);
        const float pz = (gz + 1.0f) * 0.5f * (float)(D - 1);

        const float fx = floorf(px), fy = floorf(py), fz = floorf(pz);
        const int x0 = (int)fx, y0 = (int)fy, z0 = (int)fz;
        const int x1 = x0 + 1,  y1 = y0 + 1,  z1 = z0 + 1;
        const float wx = px - fx, wy = py - fy, wz = pz - fz;

        // Zeros padding is separable: fold validity into per-axis weights.
        const float vx0 = (x0 >= 0 && x0 < W) ? (1.0f - wx) : 0.0f;
        const float vx1 = (x1 >= 0 && x1 < W) ? wx          : 0.0f;
        const float vy0 = (y0 >= 0 && y0 < H) ? (1.0f - wy) : 0.0f;
        const float vy1 = (y1 >= 0 && y1 < H) ? wy          : 0.0f;
        const float vz0 = (z0 >= 0 && z0 < D) ? (1.0f - wz) : 0.0f;
        const float vz1 = (z1 >= 0 && z1 < D) ? wz          : 0.0f;

        const int xc0 = min(max(x0, 0), W - 1);
        const int xc1 = min(max(x1, 0), W - 1);
        const int yc0 = min(max(y0, 0), H - 1);
        const int yc1 = min(max(y1, 0), H - 1);
        const int zc0 = min(max(z0, 0), D - 1);
        const int zc1 = min(max(z1, 0), D - 1);

        adr[p][0] = (zc0 * H + yc0) * W + xc0;
        adr[p][1] = (zc0 * H + yc1) * W + xc0;
        adr[p][2] = (zc1 * H + yc0) * W + xc0;
        adr[p][3] = (zc1 * H + yc1) * W + xc0;
        dx[p]     = xc1 - xc0;

        zy[p][0] = vz0 * vy0;
        zy[p][1] = vz0 * vy1;
        zy[p][2] = vz1 * vy0;
        zy[p][3] = vz1 * vy1;
        ax0[p] = vx0;
        ax1[p] = vx1;
    }

    // Write phase: thread covers rows w_rA, w_rA+16; d-lane dl.
    const int w_rA = ty * 2 + (wl >> 4);
    const int dl   = wl & 15;
    const size_t obaseA = ((size_t)((blockIdx.x * W_T + w_rA) * H + h) * C) * D + d0 + dl;
    const size_t obaseB = ((size_t)((blockIdx.x * W_T + w_rA + 16) * H + h) * C) * D + d0 + dl;

    const float* ip = in;
    for (int c = 0; c < C; c += CH) {
        const int b0 = ((c / CH) & 1) * CH;    // ring half: bufs b0..b0+3

        // ---- compute phase: CH channels, up to 64 independent gathers ----
#pragma unroll
        for (int ch = 0; ch < CH; ch++) {
            const float* ipc = ip + ch * DHW;
#pragma unroll
            for (int p = 0; p < PTS; p++) {
                const int a0 = adr[p][0], a1 = adr[p][1];
                const int a2 = adr[p][2], a3 = adr[p][3];
                const int dd = dx[p];

                const float v00 = __ldg(ipc + a0);
                const float v01 = __ldg(ipc + a0 + dd);
                const float v10 = __ldg(ipc + a1);
                const float v11 = __ldg(ipc + a1 + dd);
                const float v20 = __ldg(ipc + a2);
                const float v21 = __ldg(ipc + a2 + dd);
                const float v30 = __ldg(ipc + a3);
                const float v31 = __ldg(ipc + a3 + dd);

                float r;
                r =          zy[p][0] * fmaf(ax1[p], v01, ax0[p] * v00);
                r = fmaf(zy[p][1], fmaf(ax1[p], v11, ax0[p] * v10), r);
                r = fmaf(zy[p][2], fmaf(ax1[p], v21, ax0[p] * v20), r);
                r = fmaf(zy[p][3], fmaf(ax1[p], v31, ax0[p] * v30), r);

                s[b0 + ch][wl][ty + 8 * p] = r;
            }
        }

        __syncthreads();   // bufs ready; ring + 1 sync/iter is race-free
                           // (reuse of this half is 2 syncs away)

        // ---- write phase: contiguous-in-d stores ----
#pragma unroll
        for (int ch = 0; ch < CH; ch++) {
            const size_t co = (size_t)(c + ch) * D;
            out[obaseA + co] = s[b0 + ch][w_rA][dl];
            out[obaseB + co] = s[b0 + ch][w_rA + 16][dl];
        }

        ip += CH * DHW;
    }
}

extern "C" void kernel_launch(void* const* d_in, const int* in_sizes, int n_in,
                              void* d_out, int out_size)
{
    const float* in    = (const float*)d_in[0];   // [1,32,64,192,160]
    const float* theta = (const float*)d_in[1];   // [12]
    float* out = (float*)d_out;                   // [1,160,192,32,64]

    dim3 block(32, 8);                    // w x d-rows
    dim3 grid(W / W_T, D / D_T, H);       // 5 x 4 x 192 = 3840
    affine_grid_sample_kernel<<<grid, block>>>(in, theta, out);
}

// round 17
// speedup vs baseline: 1.3594x; 1.0080x over previous
#include <cuda_runtime.h>

constexpr int C = 32, D = 64, H = 192, W = 160;
constexpr int DHW = D * H * W;     // 1,966,080

constexpr int W_T = 32;            // tile width (w)
constexpr int D_T = 16;            // tile depth (d)
constexpr int PTS = 2;             // d-points per thread
constexpr int SP  = D_T + 1;       // padded smem row (17)
constexpr int CH  = 4;             // channels per barrier

// Block: 32 (w) x 8 (d-rows) = 256 threads, 2 points each -> 32x16 tile.
// Compute: lanes along w (coalesced gathers). Write: smem transpose ->
// stores contiguous in d. 4 channels per barrier, 8-buffer smem ring.
__global__ __launch_bounds__(256, 4)
void affine_grid_sample_kernel(const float* __restrict__ in,
                               const float* __restrict__ theta,
                               float* __restrict__ out)
{
    __shared__ float s[2 * CH][W_T][SP];

    const int wl = threadIdx.x;                 // 0..31
    const int ty = threadIdx.y;                 // 0..7
    const int w  = blockIdx.x * W_T + wl;       // 0..159
    const int d0 = blockIdx.y * D_T;            // 0,16,32,48
    const int h  = blockIdx.z;                  // 0..191

    float t[12];
#pragma unroll
    for (int i = 0; i < 12; i++) t[i] = __ldg(theta + i);

    const float xn = -1.0f + 2.0f * (float)w / (float)(W - 1);
    const float yn = -1.0f + 2.0f * (float)h / (float)(H - 1);

    // Per-point geometry held in registers across the channel loop.
    int   adr[PTS][4];       // 4 (z,y)-row bases with xc0 folded in
    int   dx[PTS];           // xc1-xc0 (0 at clamped edge, else 1)
    float zy[PTS][4];        // masked az*ay products
    float ax0[PTS], ax1[PTS];

#pragma unroll
    for (int p = 0; p < PTS; p++) {
        const int d = d0 + ty + 8 * p;
        const float zn = -1.0f + 2.0f * (float)d / (float)(D - 1);

        const float gx = t[0] * xn + t[1] * yn + t[2]  * zn + t[3];
        const float gy = t[4] * xn + t[5] * yn + t[6]  * zn + t[7];
        const float gz = t[8] * xn + t[9] * yn + t[10] * zn + t[11];

        const float px = (gx + 1.0f) * 0.5f * (float)(W - 1);
        const float py = (gy + 1.0f) * 0.5f * (float)(H - 1);
        const float pz = (gz + 1.0f) * 0.5f * (float)(D - 1);

        const float fx = floorf(px), fy = floorf(py), fz = floorf(pz);
        const int x0 = (int)fx, y0 = (int)fy, z0 = (int)fz;
        const int x1 = x0 + 1,  y1 = y0 + 1,  z1 = z0 + 1;
        const float wx = px - fx, wy = py - fy, wz = pz - fz;

        // Zeros padding is separable: fold validity into per-axis weights.
        const float vx0 = (x0 >= 0 && x0 < W) ? (1.0f - wx) : 0.0f;
        const float vx1 = (x1 >= 0 && x1 < W) ? wx          : 0.0f;
        const float vy0 = (y0 >= 0 && y0 < H) ? (1.0f - wy) : 0.0f;
        const float vy1 = (y1 >= 0 && y1 < H) ? wy          : 0.0f;
        const float vz0 = (z0 >= 0 && z0 < D) ? (1.0f - wz) : 0.0f;
        const float vz1 = (z1 >= 0 && z1 < D) ? wz          : 0.0f;

        const int xc0 = min(max(x0, 0), W - 1);
        const int xc1 = min(max(x1, 0), W - 1);
        const int yc0 = min(max(y0, 0), H - 1);
        const int yc1 = min(max(y1, 0), H - 1);
        const int zc0 = min(max(z0, 0), D - 1);
        const int zc1 = min(max(z1, 0), D - 1);

        adr[p][0] = (zc0 * H + yc0) * W + xc0;
        adr[p][1] = (zc0 * H + yc1) * W + xc0;
        adr[p][2] = (zc1 * H + yc0) * W + xc0;
        adr[p][3] = (zc1 * H + yc1) * W + xc0;
        dx[p]     = xc1 - xc0;

        zy[p][0] = vz0 * vy0;
        zy[p][1] = vz0 * vy1;
        zy[p][2] = vz1 * vy0;
        zy[p][3] = vz1 * vy1;
        ax0[p] = vx0;
        ax1[p] = vx1;
    }

    // Write phase: thread covers rows w_rA, w_rA+16; d-lane dl.
    const int w_rA = ty * 2 + (wl >> 4);
    const int dl   = wl & 15;
    const size_t obaseA = ((size_t)((blockIdx.x * W_T + w_rA) * H + h) * C) * D + d0 + dl;
    const size_t obaseB = ((size_t)((blockIdx.x * W_T + w_rA + 16) * H + h) * C) * D + d0 + dl;

    const float* ip = in;
    for (int c = 0; c < C; c += CH) {
        const int b0 = ((c / CH) & 1) * CH;    // ring half: bufs b0..b0+3

        // ---- compute phase: CH channels, up to 64 independent gathers ----
#pragma unroll
        for (int ch = 0; ch < CH; ch++) {
            const float* ipc = ip + ch * DHW;
#pragma unroll
            for (int p = 0; p < PTS; p++) {
                const int a0 = adr[p][0], a1 = adr[p][1];
                const int a2 = adr[p][2], a3 = adr[p][3];
                const int dd = dx[p];

                const float v00 = __ldg(ipc + a0);
                const float v01 = __ldg(ipc + a0 + dd);
                const float v10 = __ldg(ipc + a1);
                const float v11 = __ldg(ipc + a1 + dd);
                const float v20 = __ldg(ipc + a2);
                const float v21 = __ldg(ipc + a2 + dd);
                const float v30 = __ldg(ipc + a3);
                const float v31 = __ldg(ipc + a3 + dd);

                float r;
                r =          zy[p][0] * fmaf(ax1[p], v01, ax0[p] * v00);
                r = fmaf(zy[p][1], fmaf(ax1[p], v11, ax0[p] * v10), r);
                r = fmaf(zy[p][2], fmaf(ax1[p], v21, ax0[p] * v20), r);
                r = fmaf(zy[p][3], fmaf(ax1[p], v31, ax0[p] * v30), r);

                s[b0 + ch][wl][ty + 8 * p] = r;
            }
        }

        __syncthreads();   // bufs ready; ring + 1 sync/iter is race-free
                           // (reuse of this half is 2 syncs away)

        // ---- write phase: contiguous-in-d stores ----
#pragma unroll
        for (int ch = 0; ch < CH; ch++) {
            const size_t co = (size_t)(c + ch) * D;
            out[obaseA + co] = s[b0 + ch][w_rA][dl];
            out[obaseB + co] = s[b0 + ch][w_rA + 16][dl];
        }

        ip += CH * DHW;
    }
}

extern "C" void kernel_launch(void* const* d_in, const int* in_sizes, int n_in,
                              void* d_out, int out_size)
{
    const float* in    = (const float*)d_in[0];   // [1,32,64,192,160]
    const float* theta = (const float*)d_in[1];   // [12]
    float* out = (float*)d_out;                   // [1,160,192,32,64]

    dim3 block(32, 8);                    // w x d-rows
    dim3 grid(W / W_T, D / D_T, H);       // 5 x 4 x 192 = 3840
    affine_grid_sample_kernel<<<grid, block>>>(in, theta, out);
}